// round 14
// baseline (speedup 1.0000x reference)
#include <cuda_runtime.h>
#include <cstdint>

#define N_NODES 100000
#define N_EDGES 1600000
#define IN_DIM 512
#define H0 32
#define H1 8

// ---------------- scratch (static device globals; no allocation) ----------------
__device__ float g_srec[N_NODES * 16];  // per-node scaled: {dinv*z0..z7, dinv*p1, dinv*p2, 0..}
__device__ float g_hw2[N_NODES * 8];    // hw (h@W1); scaled in-place by dinv2 in k_deg2
__device__ float g_dinv[N_NODES];       // rsqrt(1+deg1)
__device__ float g_dinv2[N_NODES];      // rsqrt(1+deg2)
__device__ int   g_cnt[N_NODES];        // in-degree (edges only)
__device__ int   g_base[N_NODES];       // CSR segment start
__device__ int   g_woff[N_NODES];       // scatter cursor
__device__ int   g_srow[N_EDGES];       // CSR: source node per in-edge, grouped by target
__device__ float g_mw[N_EDGES];         // masked gate weight per CSR edge
__device__ float g_a1[N_NODES];
__device__ float g_a2[N_NODES];
__device__ float g_bW[8];               // b0 @ W1
__device__ float g_c0;                  // all gate bias constants folded
__device__ int   g_is64;
__device__ int   g_bsum[128];           // raw per-block sums from scan1 (98 used)
__device__ float4 g_bfrag2[64 * 2 * 32]; // Wbig tf32 frags

// ---------------- tf32 helpers ----------------
__device__ __forceinline__ uint32_t f2tf32(float f) {
    uint32_t r;
    asm("cvt.rna.tf32.f32 %0, %1;" : "=r"(r) : "f"(f));
    return r;
}

__device__ __forceinline__ void mma_tf32(float4& c, uint32_t a0, uint32_t a1,
                                         uint32_t a2, uint32_t a3,
                                         uint32_t b0, uint32_t b1) {
    asm volatile(
        "mma.sync.aligned.m16n8k8.row.col.f32.tf32.tf32.f32 "
        "{%0,%1,%2,%3}, {%4,%5,%6,%7}, {%8,%9}, {%0,%1,%2,%3};"
        : "+f"(c.x), "+f"(c.y), "+f"(c.z), "+f"(c.w)
        : "r"(a0), "r"(a1), "r"(a2), "r"(a3), "r"(b0), "r"(b1));
}

// ---------------- K0: zero histogram (blocks 0..NB-1) + prep (block NB) -------
__global__ void __launch_bounds__(1024) k_initprep(const void* __restrict__ edge_raw,
        const float* __restrict__ W0, const float* __restrict__ b0,
        const float* __restrict__ W1,
        const float* __restrict__ Wnb, const float* __restrict__ bnb,
        const float* __restrict__ Wself, const float* __restrict__ bself,
        const float* __restrict__ Watt, const float* __restrict__ batt,
        int N, int NB) {
    __shared__ float swb[512 * 16];   // 32KB
    __shared__ float swa1[32], swa2[32];
    if ((int)blockIdx.x < NB) {
        int i = blockIdx.x * 1024 + threadIdx.x;
        if (i < N) g_cnt[i] = 0;
        return;
    }
    int t = threadIdx.x;

    if (t < 32) {
        float s1 = 0.f, s2 = 0.f;
        #pragma unroll
        for (int j = 0; j < 8; j++) {
            s1 += Wnb[t * 8 + j] * Watt[j];
            s2 += Wself[t * 8 + j] * Watt[8 + j];
        }
        swa1[t] = s1; swa2[t] = s2;
    }
    __syncthreads();

    if (t == 0) {
        float c = batt[0];
        #pragma unroll
        for (int j = 0; j < 8; j++) c += bnb[j] * Watt[j] + bself[j] * Watt[8 + j];
        for (int cc = 0; cc < 32; cc++) c += b0[cc] * (swa1[cc] + swa2[cc]);
        g_c0 = c;
        const int* p = (const int*)edge_raw;
        int is64 = 1;
        for (int s = 1; s < 128; s += 2) if (p[s] != 0) { is64 = 0; break; }
        g_is64 = is64;
    }
    if (t < 8) {
        float s = 0.f;
        for (int c = 0; c < 32; c++) s += b0[c] * W1[c * 8 + t];
        g_bW[t] = s;
    }

    if (t < 512) {   // Wbig row k = t
        int k = t;
        float w0r[32];
        #pragma unroll
        for (int c = 0; c < 32; c++) w0r[c] = W0[k * 32 + c];
        #pragma unroll
        for (int j = 0; j < 8; j++) {
            float s = 0.f;
            #pragma unroll
            for (int c = 0; c < 32; c++) s += w0r[c] * W1[c * 8 + j];
            swb[k * 16 + j] = s;
        }
        float s1 = 0.f, s2 = 0.f;
        #pragma unroll
        for (int c = 0; c < 32; c++) { s1 += w0r[c] * swa1[c]; s2 += w0r[c] * swa2[c]; }
        swb[k * 16 + 8] = s1;
        swb[k * 16 + 9] = s2;
        #pragma unroll
        for (int j = 10; j < 16; j++) swb[k * 16 + j] = 0.f;
    }
    __syncthreads();

    // bake tf32 hi/lo B-fragments: 64 chunks x 2 ntiles x 32 lanes
    for (int i = t; i < 64 * 2 * 32; i += 1024) {
        int lane = i & 31;
        int nt = (i >> 5) & 1;
        int chunk = i >> 6;
        int gid = lane >> 2, tig = lane & 3;
        int n = nt * 8 + gid;
        int k = chunk * 8 + tig;
        float b0f = swb[k * 16 + n];
        float b1f = swb[(k + 4) * 16 + n];
        uint32_t h0 = f2tf32(b0f);
        uint32_t h1 = f2tf32(b1f);
        uint32_t l0 = f2tf32(b0f - __uint_as_float(h0));
        uint32_t l1 = f2tf32(b1f - __uint_as_float(h1));
        g_bfrag2[i] = make_float4(__uint_as_float(h0), __uint_as_float(h1),
                                  __uint_as_float(l0), __uint_as_float(l1));
    }
}

// ---------------- K1: in-degree histogram (reads col half of raw edges) -------
__global__ void k_convert(const void* __restrict__ edge_raw, int E) {
    int e = blockIdx.x * blockDim.x + threadIdx.x;
    if (e >= E) return;
    int c;
    if (g_is64) {
        const long long* p = (const long long*)edge_raw;
        c = (int)p[E + e];
    } else {
        const int* p = (const int*)edge_raw;
        c = p[E + e];
    }
    atomicAdd(&g_cnt[c], 1);
}

// ---------------- scan pass 1: per-block exclusive scan + raw block sums ------
__global__ void __launch_bounds__(1024) k_scan1(int N) {
    __shared__ int s[2048];
    int t = threadIdx.x;
    int i = blockIdx.x * 1024 + t;
    int v = (i < N) ? g_cnt[i] : 0;
    s[t] = v;
    __syncthreads();
    int p = 0;
    #pragma unroll
    for (int off = 1; off < 1024; off <<= 1) {
        int x = s[p + t];
        if (t >= off) x += s[p + t - off];
        p ^= 1024;
        s[p + t] = x;
        __syncthreads();
    }
    int inc = s[p + t];
    if (i < N) g_base[i] = inc - v;
    if (t == 1023) g_bsum[blockIdx.x] = inc;
}

// ---------------- scan pass 2+3 fused: per-block prefix via redundant reduce --
__global__ void __launch_bounds__(1024) k_scan3(int N) {
    __shared__ int red[128];
    __shared__ int soff;
    int t = threadIdx.x;
    int b = blockIdx.x;
    if (t < 128) red[t] = (t < b) ? g_bsum[t] : 0;
    __syncthreads();
    if (t < 64) red[t] += red[t + 64];
    __syncthreads();
    if (t < 32) {
        int v = red[t] + red[t + 32];
        #pragma unroll
        for (int o = 16; o; o >>= 1) v += __shfl_xor_sync(0xffffffffu, v, o);
        if (t == 0) soff = v;
    }
    __syncthreads();
    int i = b * 1024 + t;
    if (i >= N) return;
    int base = g_base[i] + soff;
    g_base[i] = base;
    g_woff[i] = base;
    g_dinv[i] = rsqrtf(1.f + (float)g_cnt[i]);
}

// ---------------- K2: scatter edges into CSR (reads raw row+col) --------------
__global__ void k_scatter(const void* __restrict__ edge_raw, int E) {
    int e = blockIdx.x * blockDim.x + threadIdx.x;
    if (e >= E) return;
    int r, c;
    if (g_is64) {
        const long long* p = (const long long*)edge_raw;
        r = (int)p[e]; c = (int)p[E + e];
    } else {
        const int* p = (const int*)edge_raw;
        r = p[e]; c = p[E + e];
    }
    int pos = atomicAdd(&g_woff[c], 1);
    g_srow[pos] = r;
}

// ---------------- K3: srec = dinv * (x @ Wbig), tf32 TC, direct-LDG streaming -
// block: 256 threads / 8 warps; warp = 16 rows x 16 cols. No smem, no syncs.
__global__ void __launch_bounds__(256) k_gemm3(const float* __restrict__ x, int N) {
    int tid = threadIdx.x;
    int warp = tid >> 5;
    int lane = tid & 31;
    int gid = lane >> 2;   // 0..7
    int tig = lane & 3;    // 0..3
    int r0 = blockIdx.x * 128 + warp * 16 + gid;
    int r1 = r0 + 8;
    int rr0 = min(r0, N - 1);
    int rr1 = min(r1, N - 1);
    const float* pa0 = x + (size_t)rr0 * IN_DIM + tig;
    const float* pa1 = x + (size_t)rr1 * IN_DIM + tig;

    float4 C[2];
    C[0] = make_float4(0.f, 0.f, 0.f, 0.f);
    C[1] = make_float4(0.f, 0.f, 0.f, 0.f);

    #pragma unroll 4
    for (int c = 0; c < 64; c++) {
        // A fragment direct from global: rows gid/gid+8, cols c*8+tig, c*8+tig+4
        float f0 = pa0[c * 8];
        float f1 = pa1[c * 8];
        float f2 = pa0[c * 8 + 4];
        float f3 = pa1[c * 8 + 4];
        uint32_t ah0 = f2tf32(f0), ah1 = f2tf32(f1), ah2 = f2tf32(f2), ah3 = f2tf32(f3);
        uint32_t al0 = f2tf32(f0 - __uint_as_float(ah0));
        uint32_t al1 = f2tf32(f1 - __uint_as_float(ah1));
        uint32_t al2 = f2tf32(f2 - __uint_as_float(ah2));
        uint32_t al3 = f2tf32(f3 - __uint_as_float(ah3));
        #pragma unroll
        for (int nt = 0; nt < 2; nt++) {
            float4 bf = g_bfrag2[(c * 2 + nt) * 32 + lane];
            uint32_t bh0 = __float_as_uint(bf.x), bh1 = __float_as_uint(bf.y);
            uint32_t bl0 = __float_as_uint(bf.z), bl1 = __float_as_uint(bf.w);
            mma_tf32(C[nt], ah0, ah1, ah2, ah3, bl0, bl1);  // hi*lo
            mma_tf32(C[nt], al0, al1, al2, al3, bh0, bh1);  // lo*hi
            mma_tf32(C[nt], ah0, ah1, ah2, ah3, bh0, bh1);  // hi*hi
        }
    }

    // epilogue: srec[r] = dinv[r] * {z0..7, p1, p2}, padded to 16 floats
    if (r0 < N) {
        float sc = g_dinv[r0];
        float2* p = (float2*)&g_srec[r0 * 16];
        p[tig] = make_float2(sc * C[0].x, sc * C[0].y);
        if (tig == 0) p[4] = make_float2(sc * C[1].x, sc * C[1].y);  // sp1, sp2
        if (tig == 1) p[5] = make_float2(0.f, 0.f);
    }
    if (r1 < N) {
        float sc = g_dinv[r1];
        float2* p = (float2*)&g_srec[r1 * 16];
        p[tig] = make_float2(sc * C[0].z, sc * C[0].w);
        if (tig == 0) p[4] = make_float2(sc * C[1].z, sc * C[1].w);
        if (tig == 1) p[5] = make_float2(0.f, 0.f);
    }
}

// ---------------- K4: conv1 gather (pure ADD, unroll x2) ---------------------
// 4 lanes per node: lanes 0,1 = z halves; lane 2 = {sp1,sp2,0,0}; lane 3 idle.
__global__ void __launch_bounds__(256) k_conv1(int N) {
    int t = blockIdx.x * blockDim.x + threadIdx.x;
    int n = t >> 2;
    if (n >= N) return;
    int j = threadIdx.x & 3;
    const float4* rec4 = (const float4*)g_srec;

    float4 acc = make_float4(0.f, 0.f, 0.f, 0.f);
    float4 acc2 = make_float4(0.f, 0.f, 0.f, 0.f);
    if (j < 3) acc = rec4[n * 4 + j];   // self-loop term (pre-scaled)

    int s0 = g_base[n], cnt = g_cnt[n];
    int i = 0;
    for (; i + 2 <= cnt; i += 2) {
        int r0 = g_srow[s0 + i];
        int r1 = g_srow[s0 + i + 1];
        if (j < 3) {
            float4 v0 = rec4[r0 * 4 + j];
            float4 v1 = rec4[r1 * 4 + j];
            acc.x += v0.x; acc.y += v0.y; acc.z += v0.z; acc.w += v0.w;
            acc2.x += v1.x; acc2.y += v1.y; acc2.z += v1.z; acc2.w += v1.w;
        }
    }
    if (i < cnt) {
        int r0 = g_srow[s0 + i];
        if (j < 3) {
            float4 v0 = rec4[r0 * 4 + j];
            acc.x += v0.x; acc.y += v0.y; acc.z += v0.z; acc.w += v0.w;
        }
    }
    acc.x += acc2.x; acc.y += acc2.y; acc.z += acc2.z; acc.w += acc2.w;

    float dc = g_dinv[n];
    if (j < 2) {
        float4 bw = ((const float4*)g_bW)[j];
        float4 hw;
        hw.x = fmaf(dc, acc.x, bw.x);
        hw.y = fmaf(dc, acc.y, bw.y);
        hw.z = fmaf(dc, acc.z, bw.z);
        hw.w = fmaf(dc, acc.w, bw.w);
        ((float4*)g_hw2)[n * 2 + j] = hw;
    } else if (j == 2) {
        g_a1[n] = dc * acc.x;
        g_a2[n] = dc * acc.y;
    }
}

// ---------------- K5: deg2 + per-edge gate weights + scale hw2 in place ------
__global__ void __launch_bounds__(256) k_deg2(int N) {
    int t = blockIdx.x * blockDim.x + threadIdx.x;
    int n = t >> 2;
    if (n >= N) return;
    int lane = threadIdx.x & 31;
    int l = lane & 3;
    unsigned mask = 0xFu << (lane & ~3);
    float a2c = g_a2[n] + g_c0;
    int s0 = g_base[n], cnt = g_cnt[n];
    float sum = 0.f;
    for (int i = l; i < cnt; i += 4) {
        int r = g_srow[s0 + i];
        float w = g_a1[r] + a2c;
        float mw = 0.f;
        if (w > 0.f) {
            float m = fminf(1.01f / (1.f + __expf(-w)), 1.f);
            mw = m * w;
            sum += mw;
        }
        g_mw[s0 + i] = mw;
    }
    sum += __shfl_xor_sync(mask, sum, 1);
    sum += __shfl_xor_sync(mask, sum, 2);
    float d2 = rsqrtf(1.f + sum);
    if (l == 0) g_dinv2[n] = d2;
    if (l < 2) {                        // scale hw in place: s_hw = dinv2 * hw
        float4 v = ((const float4*)g_hw2)[n * 2 + l];
        v.x *= d2; v.y *= d2; v.z *= d2; v.w *= d2;
        ((float4*)g_hw2)[n * 2 + l] = v;
    }
}

// ---------------- K6: conv2 gather -> out (2 lanes/node, unroll x2) ----------
__global__ void __launch_bounds__(256) k_conv2(float* __restrict__ out,
                                               const float* __restrict__ b1, int N) {
    int t = blockIdx.x * blockDim.x + threadIdx.x;
    int n = t >> 1;
    if (n >= N) return;
    int j = t & 1;
    const float4* hw4 = (const float4*)g_hw2;

    float4 acc = hw4[n * 2 + j];        // self term (pre-scaled by dinv2)
    float4 acc2 = make_float4(0.f, 0.f, 0.f, 0.f);
    int s0 = g_base[n], cnt = g_cnt[n];
    int i = 0;
    for (; i + 2 <= cnt; i += 2) {
        float mw0 = g_mw[s0 + i];
        float mw1 = g_mw[s0 + i + 1];
        if (mw0 != 0.f) {
            int r = g_srow[s0 + i];
            float4 v = hw4[r * 2 + j];
            acc.x = fmaf(mw0, v.x, acc.x);
            acc.y = fmaf(mw0, v.y, acc.y);
            acc.z = fmaf(mw0, v.z, acc.z);
            acc.w = fmaf(mw0, v.w, acc.w);
        }
        if (mw1 != 0.f) {
            int r = g_srow[s0 + i + 1];
            float4 v = hw4[r * 2 + j];
            acc2.x = fmaf(mw1, v.x, acc2.x);
            acc2.y = fmaf(mw1, v.y, acc2.y);
            acc2.z = fmaf(mw1, v.z, acc2.z);
            acc2.w = fmaf(mw1, v.w, acc2.w);
        }
    }
    if (i < cnt) {
        float mw0 = g_mw[s0 + i];
        if (mw0 != 0.f) {
            int r = g_srow[s0 + i];
            float4 v = hw4[r * 2 + j];
            acc.x = fmaf(mw0, v.x, acc.x);
            acc.y = fmaf(mw0, v.y, acc.y);
            acc.z = fmaf(mw0, v.z, acc.z);
            acc.w = fmaf(mw0, v.w, acc.w);
        }
    }
    acc.x += acc2.x; acc.y += acc2.y; acc.z += acc2.z; acc.w += acc2.w;

    float d2n = g_dinv2[n];
    float4 bb = ((const float4*)b1)[j];
    float4 o;
    o.x = fmaf(d2n, acc.x, bb.x);
    o.y = fmaf(d2n, acc.y, bb.y);
    o.z = fmaf(d2n, acc.z, bb.z);
    o.w = fmaf(d2n, acc.w, bb.w);
    ((float4*)out)[n * 2 + j] = o;
}

// ---------------- launch ----------------
extern "C" void kernel_launch(void* const* d_in, const int* in_sizes, int n_in,
                              void* d_out, int out_size) {
    const float* x     = (const float*)d_in[0];
    const void*  eidx  = d_in[1];
    const float* W0    = (const float*)d_in[2];
    const float* b0    = (const float*)d_in[3];
    const float* W1    = (const float*)d_in[4];
    const float* b1    = (const float*)d_in[5];
    const float* Wnb   = (const float*)d_in[6];
    const float* bnb   = (const float*)d_in[7];
    const float* Wself = (const float*)d_in[8];
    const float* bself = (const float*)d_in[9];
    const float* Watt  = (const float*)d_in[10];
    const float* batt  = (const float*)d_in[11];
    float* out = (float*)d_out;

    int N = in_sizes[0] / IN_DIM;
    int E = in_sizes[1] / 2;
    int NB = (N + 1023) / 1024;

    k_initprep<<<NB + 1, 1024>>>(eidx, W0, b0, W1, Wnb, bnb, Wself, bself,
                                 Watt, batt, N, NB);
    k_convert<<<(E + 255) / 256, 256>>>(eidx, E);
    k_scan1<<<NB, 1024>>>(N);
    k_scan3<<<NB, 1024>>>(N);
    k_scatter<<<(E + 255) / 256, 256>>>(eidx, E);
    k_gemm3<<<(N + 127) / 128, 256>>>(x, N);
    k_conv1<<<(N * 4 + 255) / 256, 256>>>(N);
    k_deg2<<<(N * 4 + 255) / 256, 256>>>(N);
    k_conv2<<<(N * 2 + 255) / 256, 256>>>(out, b1, N);
}

// round 16
// speedup vs baseline: 1.0976x; 1.0976x over previous
#include <cuda_runtime.h>
#include <cstdint>

#define N_NODES 100000
#define N_EDGES 1600000
#define IN_DIM 512
#define H0 32
#define H1 8

// ---------------- scratch (static device globals; no allocation) ----------------
__device__ float g_srec[N_NODES * 16];  // per-node scaled: {dinv*z0..z7, dinv*p1, dinv*p2, 0..}
__device__ float g_hw2[N_NODES * 8];    // hw (h@W1); scaled in-place by dinv2 in k_deg2
__device__ float g_dinv[N_NODES];       // rsqrt(1+deg1)
__device__ float g_dinv2[N_NODES];      // rsqrt(1+deg2)
__device__ int   g_cnt[N_NODES];        // in-degree (edges only)
__device__ int   g_base[N_NODES];       // CSR segment start
__device__ int   g_woff[N_NODES];       // scatter cursor
__device__ int   g_srow[N_EDGES];       // CSR: source node per in-edge, grouped by target
__device__ float g_mw[N_EDGES];         // masked gate weight per CSR edge
__device__ float g_a1[N_NODES];
__device__ float g_a2[N_NODES];
__device__ float g_bW[8];               // b0 @ W1
__device__ float g_c0;                  // all gate bias constants folded
__device__ int   g_is64;
__device__ int   g_bsum[128];           // raw per-block sums from scan1 (98 used)
__device__ float4 g_bfrag2[64 * 2 * 32]; // Wbig tf32 frags

// ---------------- tf32 helpers ----------------
__device__ __forceinline__ uint32_t f2tf32(float f) {
    uint32_t r;
    asm("cvt.rna.tf32.f32 %0, %1;" : "=r"(r) : "f"(f));
    return r;
}

__device__ __forceinline__ void mma_tf32(float4& c, uint32_t a0, uint32_t a1,
                                         uint32_t a2, uint32_t a3,
                                         uint32_t b0, uint32_t b1) {
    asm volatile(
        "mma.sync.aligned.m16n8k8.row.col.f32.tf32.tf32.f32 "
        "{%0,%1,%2,%3}, {%4,%5,%6,%7}, {%8,%9}, {%0,%1,%2,%3};"
        : "+f"(c.x), "+f"(c.y), "+f"(c.z), "+f"(c.w)
        : "r"(a0), "r"(a1), "r"(a2), "r"(a3), "r"(b0), "r"(b1));
}

// ---------------- K0: zero histogram (blocks 0..NB-1) + prep (block NB) -------
__global__ void __launch_bounds__(1024) k_initprep(const void* __restrict__ edge_raw,
        const float* __restrict__ W0, const float* __restrict__ b0,
        const float* __restrict__ W1,
        const float* __restrict__ Wnb, const float* __restrict__ bnb,
        const float* __restrict__ Wself, const float* __restrict__ bself,
        const float* __restrict__ Watt, const float* __restrict__ batt,
        int N, int NB) {
    __shared__ float swb[512 * 16];   // 32KB
    __shared__ float swa1[32], swa2[32];
    if ((int)blockIdx.x < NB) {
        int i = blockIdx.x * 1024 + threadIdx.x;
        if (i < N) g_cnt[i] = 0;
        return;
    }
    int t = threadIdx.x;

    if (t < 32) {
        float s1 = 0.f, s2 = 0.f;
        #pragma unroll
        for (int j = 0; j < 8; j++) {
            s1 += Wnb[t * 8 + j] * Watt[j];
            s2 += Wself[t * 8 + j] * Watt[8 + j];
        }
        swa1[t] = s1; swa2[t] = s2;
    }
    __syncthreads();

    if (t == 0) {
        float c = batt[0];
        #pragma unroll
        for (int j = 0; j < 8; j++) c += bnb[j] * Watt[j] + bself[j] * Watt[8 + j];
        for (int cc = 0; cc < 32; cc++) c += b0[cc] * (swa1[cc] + swa2[cc]);
        g_c0 = c;
        const int* p = (const int*)edge_raw;
        int is64 = 1;
        for (int s = 1; s < 128; s += 2) if (p[s] != 0) { is64 = 0; break; }
        g_is64 = is64;
    }
    if (t < 8) {
        float s = 0.f;
        for (int c = 0; c < 32; c++) s += b0[c] * W1[c * 8 + t];
        g_bW[t] = s;
    }

    if (t < 512) {   // Wbig row k = t
        int k = t;
        float w0r[32];
        #pragma unroll
        for (int c = 0; c < 32; c++) w0r[c] = W0[k * 32 + c];
        #pragma unroll
        for (int j = 0; j < 8; j++) {
            float s = 0.f;
            #pragma unroll
            for (int c = 0; c < 32; c++) s += w0r[c] * W1[c * 8 + j];
            swb[k * 16 + j] = s;
        }
        float s1 = 0.f, s2 = 0.f;
        #pragma unroll
        for (int c = 0; c < 32; c++) { s1 += w0r[c] * swa1[c]; s2 += w0r[c] * swa2[c]; }
        swb[k * 16 + 8] = s1;
        swb[k * 16 + 9] = s2;
        #pragma unroll
        for (int j = 10; j < 16; j++) swb[k * 16 + j] = 0.f;
    }
    __syncthreads();

    // bake tf32 hi/lo B-fragments: 64 chunks x 2 ntiles x 32 lanes
    for (int i = t; i < 64 * 2 * 32; i += 1024) {
        int lane = i & 31;
        int nt = (i >> 5) & 1;
        int chunk = i >> 6;
        int gid = lane >> 2, tig = lane & 3;
        int n = nt * 8 + gid;
        int k = chunk * 8 + tig;
        float b0f = swb[k * 16 + n];
        float b1f = swb[(k + 4) * 16 + n];
        uint32_t h0 = f2tf32(b0f);
        uint32_t h1 = f2tf32(b1f);
        uint32_t l0 = f2tf32(b0f - __uint_as_float(h0));
        uint32_t l1 = f2tf32(b1f - __uint_as_float(h1));
        g_bfrag2[i] = make_float4(__uint_as_float(h0), __uint_as_float(h1),
                                  __uint_as_float(l0), __uint_as_float(l1));
    }
}

// ---------------- K1: in-degree histogram (reads col half of raw edges) -------
__global__ void k_convert(const void* __restrict__ edge_raw, int E) {
    int e = blockIdx.x * blockDim.x + threadIdx.x;
    if (e >= E) return;
    int c;
    if (g_is64) {
        const long long* p = (const long long*)edge_raw;
        c = (int)p[E + e];
    } else {
        const int* p = (const int*)edge_raw;
        c = p[E + e];
    }
    atomicAdd(&g_cnt[c], 1);
}

// ---------------- scan pass 1: per-block exclusive scan + raw block sums ------
__global__ void __launch_bounds__(1024) k_scan1(int N) {
    __shared__ int s[2048];
    int t = threadIdx.x;
    int i = blockIdx.x * 1024 + t;
    int v = (i < N) ? g_cnt[i] : 0;
    s[t] = v;
    __syncthreads();
    int p = 0;
    #pragma unroll
    for (int off = 1; off < 1024; off <<= 1) {
        int x = s[p + t];
        if (t >= off) x += s[p + t - off];
        p ^= 1024;
        s[p + t] = x;
        __syncthreads();
    }
    int inc = s[p + t];
    if (i < N) g_base[i] = inc - v;
    if (t == 1023) g_bsum[blockIdx.x] = inc;
}

// ---------------- scan pass 2+3 fused: per-block prefix via redundant reduce --
__global__ void __launch_bounds__(1024) k_scan3(int N) {
    __shared__ int red[128];
    __shared__ int soff;
    int t = threadIdx.x;
    int b = blockIdx.x;
    if (t < 128) red[t] = (t < b) ? g_bsum[t] : 0;
    __syncthreads();
    if (t < 64) red[t] += red[t + 64];
    __syncthreads();
    if (t < 32) {
        int v = red[t] + red[t + 32];
        #pragma unroll
        for (int o = 16; o; o >>= 1) v += __shfl_xor_sync(0xffffffffu, v, o);
        if (t == 0) soff = v;
    }
    __syncthreads();
    int i = b * 1024 + t;
    if (i >= N) return;
    int base = g_base[i] + soff;
    g_base[i] = base;
    g_woff[i] = base;
    g_dinv[i] = rsqrtf(1.f + (float)g_cnt[i]);
}

// ---------------- K3: merged GEMM + scatter -----------------------------------
// blocks [0, GB): srec = dinv * (x @ Wbig), tf32 TC, 3-stage cp.async pipeline
// blocks [GB, ...): scatter edges into CSR (reads raw row+col)
// Scatter is latency-bound and fills warp slots while GEMM bounds the kernel.
#define GEMM_STG (128 * 36)
__global__ void __launch_bounds__(256, 4) k_gemm_scatter(const float* __restrict__ x,
                                                         const void* __restrict__ edge_raw,
                                                         int N, int E, int GB) {
    extern __shared__ float sA[];   // 3 * GEMM_STG floats = 54KB (GEMM blocks only)

    if ((int)blockIdx.x >= GB) {
        // ----- scatter path -----
        int e = (blockIdx.x - GB) * 256 + threadIdx.x;
        if (e >= E) return;
        int r, c;
        if (g_is64) {
            const long long* p = (const long long*)edge_raw;
            r = (int)p[e]; c = (int)p[E + e];
        } else {
            const int* p = (const int*)edge_raw;
            r = p[e]; c = p[E + e];
        }
        int pos = atomicAdd(&g_woff[c], 1);
        g_srow[pos] = r;
        return;
    }

    // ----- GEMM path -----
    int tid = threadIdx.x;
    int warp = tid >> 5;
    int lane = tid & 31;
    int gid = lane >> 2;   // 0..7
    int tig = lane & 3;    // 0..3
    int row0 = blockIdx.x * 128;
    int wr0 = warp * 16;
    bool full = (row0 + 128 <= N);

    float4 C[2];
    C[0] = make_float4(0.f, 0.f, 0.f, 0.f);
    C[1] = make_float4(0.f, 0.f, 0.f, 0.f);

    auto issue_stage = [&](int buf, int kc) {
        float* sbase = sA + buf * GEMM_STG;
        #pragma unroll
        for (int i = 0; i < 4; i++) {
            int idx = tid + i * 256;
            int r = idx >> 3;
            int cg = idx & 7;
            int grow = row0 + r;
            float* dgen = &sbase[r * 36 + cg * 4];
            uint32_t dst = (uint32_t)__cvta_generic_to_shared(dgen);
            const float* src = &x[(size_t)grow * IN_DIM + kc + cg * 4];
            if (full || grow < N) {
                asm volatile("cp.async.cg.shared.global [%0], [%1], 16;"
                             :: "r"(dst), "l"(src));
            } else {
                *(float4*)dgen = make_float4(0.f, 0.f, 0.f, 0.f);
            }
        }
        asm volatile("cp.async.commit_group;");
    };

    issue_stage(0, 0);
    issue_stage(1, 32);

    for (int s = 0; s < 16; s++) {
        if (s > 0) __syncthreads();   // compute(s-1) done -> its buffer refillable
        if (s + 2 < 16) {
            issue_stage((s + 2) % 3, (s + 2) * 32);
            asm volatile("cp.async.wait_group 2;");
        } else if (s + 1 < 16) {
            asm volatile("cp.async.wait_group 1;");
        } else {
            asm volatile("cp.async.wait_group 0;");
        }
        __syncthreads();

        const float* A = sA + (s % 3) * GEMM_STG;
        #pragma unroll
        for (int ch = 0; ch < 4; ch++) {
            int k0 = ch * 8;
            int gchunk = s * 4 + ch;
            int rb = (wr0 + gid) * 36;
            float f0 = A[rb + k0 + tig];
            float f1 = A[rb + 8 * 36 + k0 + tig];
            float f2 = A[rb + k0 + tig + 4];
            float f3 = A[rb + 8 * 36 + k0 + tig + 4];
            uint32_t ah0 = f2tf32(f0), ah1 = f2tf32(f1), ah2 = f2tf32(f2), ah3 = f2tf32(f3);
            uint32_t al0 = f2tf32(f0 - __uint_as_float(ah0));
            uint32_t al1 = f2tf32(f1 - __uint_as_float(ah1));
            uint32_t al2 = f2tf32(f2 - __uint_as_float(ah2));
            uint32_t al3 = f2tf32(f3 - __uint_as_float(ah3));
            #pragma unroll
            for (int nt = 0; nt < 2; nt++) {
                float4 bf = g_bfrag2[(gchunk * 2 + nt) * 32 + lane];
                uint32_t bh0 = __float_as_uint(bf.x), bh1 = __float_as_uint(bf.y);
                uint32_t bl0 = __float_as_uint(bf.z), bl1 = __float_as_uint(bf.w);
                mma_tf32(C[nt], ah0, ah1, ah2, ah3, bl0, bl1);  // hi*lo
                mma_tf32(C[nt], al0, al1, al2, al3, bh0, bh1);  // lo*hi
                mma_tf32(C[nt], ah0, ah1, ah2, ah3, bh0, bh1);  // hi*hi
            }
        }
    }

    // epilogue: srec[r] = dinv[r] * {z0..7, p1, p2}, padded to 16 floats
    int r0 = row0 + wr0 + gid;
    int r1 = r0 + 8;
    if (r0 < N) {
        float sc = g_dinv[r0];
        float2* p = (float2*)&g_srec[r0 * 16];
        p[tig] = make_float2(sc * C[0].x, sc * C[0].y);
        if (tig == 0) p[4] = make_float2(sc * C[1].x, sc * C[1].y);  // sp1, sp2
        if (tig == 1) p[5] = make_float2(0.f, 0.f);
    }
    if (r1 < N) {
        float sc = g_dinv[r1];
        float2* p = (float2*)&g_srec[r1 * 16];
        p[tig] = make_float2(sc * C[0].z, sc * C[0].w);
        if (tig == 0) p[4] = make_float2(sc * C[1].z, sc * C[1].w);
        if (tig == 1) p[5] = make_float2(0.f, 0.f);
    }
}

// ---------------- K4: conv1 gather (pure ADD, unroll x2) ---------------------
// 4 lanes per node: lanes 0,1 = z halves; lane 2 = {sp1,sp2,0,0}; lane 3 idle.
__global__ void __launch_bounds__(256) k_conv1(int N) {
    int t = blockIdx.x * blockDim.x + threadIdx.x;
    int n = t >> 2;
    if (n >= N) return;
    int j = threadIdx.x & 3;
    const float4* rec4 = (const float4*)g_srec;

    float4 acc = make_float4(0.f, 0.f, 0.f, 0.f);
    float4 acc2 = make_float4(0.f, 0.f, 0.f, 0.f);
    if (j < 3) acc = rec4[n * 4 + j];   // self-loop term (pre-scaled)

    int s0 = g_base[n], cnt = g_cnt[n];
    int i = 0;
    for (; i + 2 <= cnt; i += 2) {
        int r0 = g_srow[s0 + i];
        int r1 = g_srow[s0 + i + 1];
        if (j < 3) {
            float4 v0 = rec4[r0 * 4 + j];
            float4 v1 = rec4[r1 * 4 + j];
            acc.x += v0.x; acc.y += v0.y; acc.z += v0.z; acc.w += v0.w;
            acc2.x += v1.x; acc2.y += v1.y; acc2.z += v1.z; acc2.w += v1.w;
        }
    }
    if (i < cnt) {
        int r0 = g_srow[s0 + i];
        if (j < 3) {
            float4 v0 = rec4[r0 * 4 + j];
            acc.x += v0.x; acc.y += v0.y; acc.z += v0.z; acc.w += v0.w;
        }
    }
    acc.x += acc2.x; acc.y += acc2.y; acc.z += acc2.z; acc.w += acc2.w;

    float dc = g_dinv[n];
    if (j < 2) {
        float4 bw = ((const float4*)g_bW)[j];
        float4 hw;
        hw.x = fmaf(dc, acc.x, bw.x);
        hw.y = fmaf(dc, acc.y, bw.y);
        hw.z = fmaf(dc, acc.z, bw.z);
        hw.w = fmaf(dc, acc.w, bw.w);
        ((float4*)g_hw2)[n * 2 + j] = hw;
    } else if (j == 2) {
        g_a1[n] = dc * acc.x;
        g_a2[n] = dc * acc.y;
    }
}

// ---------------- K5: deg2 + per-edge gate weights + scale hw2 in place ------
__global__ void __launch_bounds__(256) k_deg2(int N) {
    int t = blockIdx.x * blockDim.x + threadIdx.x;
    int n = t >> 2;
    if (n >= N) return;
    int lane = threadIdx.x & 31;
    int l = lane & 3;
    unsigned mask = 0xFu << (lane & ~3);
    float a2c = g_a2[n] + g_c0;
    int s0 = g_base[n], cnt = g_cnt[n];
    float sum = 0.f;
    for (int i = l; i < cnt; i += 4) {
        int r = g_srow[s0 + i];
        float w = g_a1[r] + a2c;
        float mw = 0.f;
        if (w > 0.f) {
            float m = fminf(1.01f / (1.f + __expf(-w)), 1.f);
            mw = m * w;
            sum += mw;
        }
        g_mw[s0 + i] = mw;
    }
    sum += __shfl_xor_sync(mask, sum, 1);
    sum += __shfl_xor_sync(mask, sum, 2);
    float d2 = rsqrtf(1.f + sum);
    if (l == 0) g_dinv2[n] = d2;
    if (l < 2) {                        // scale hw in place: s_hw = dinv2 * hw
        float4 v = ((const float4*)g_hw2)[n * 2 + l];
        v.x *= d2; v.y *= d2; v.z *= d2; v.w *= d2;
        ((float4*)g_hw2)[n * 2 + l] = v;
    }
}

// ---------------- K6: conv2 gather -> out (2 lanes/node, unroll x2) ----------
__global__ void __launch_bounds__(256) k_conv2(float* __restrict__ out,
                                               const float* __restrict__ b1, int N) {
    int t = blockIdx.x * blockDim.x + threadIdx.x;
    int n = t >> 1;
    if (n >= N) return;
    int j = t & 1;
    const float4* hw4 = (const float4*)g_hw2;

    float4 acc = hw4[n * 2 + j];        // self term (pre-scaled by dinv2)
    float4 acc2 = make_float4(0.f, 0.f, 0.f, 0.f);
    int s0 = g_base[n], cnt = g_cnt[n];
    int i = 0;
    for (; i + 2 <= cnt; i += 2) {
        float mw0 = g_mw[s0 + i];
        float mw1 = g_mw[s0 + i + 1];
        if (mw0 != 0.f) {
            int r = g_srow[s0 + i];
            float4 v = hw4[r * 2 + j];
            acc.x = fmaf(mw0, v.x, acc.x);
            acc.y = fmaf(mw0, v.y, acc.y);
            acc.z = fmaf(mw0, v.z, acc.z);
            acc.w = fmaf(mw0, v.w, acc.w);
        }
        if (mw1 != 0.f) {
            int r = g_srow[s0 + i + 1];
            float4 v = hw4[r * 2 + j];
            acc2.x = fmaf(mw1, v.x, acc2.x);
            acc2.y = fmaf(mw1, v.y, acc2.y);
            acc2.z = fmaf(mw1, v.z, acc2.z);
            acc2.w = fmaf(mw1, v.w, acc2.w);
        }
    }
    if (i < cnt) {
        float mw0 = g_mw[s0 + i];
        if (mw0 != 0.f) {
            int r = g_srow[s0 + i];
            float4 v = hw4[r * 2 + j];
            acc.x = fmaf(mw0, v.x, acc.x);
            acc.y = fmaf(mw0, v.y, acc.y);
            acc.z = fmaf(mw0, v.z, acc.z);
            acc.w = fmaf(mw0, v.w, acc.w);
        }
    }
    acc.x += acc2.x; acc.y += acc2.y; acc.z += acc2.z; acc.w += acc2.w;

    float d2n = g_dinv2[n];
    float4 bb = ((const float4*)b1)[j];
    float4 o;
    o.x = fmaf(d2n, acc.x, bb.x);
    o.y = fmaf(d2n, acc.y, bb.y);
    o.z = fmaf(d2n, acc.z, bb.z);
    o.w = fmaf(d2n, acc.w, bb.w);
    ((float4*)out)[n * 2 + j] = o;
}

// ---------------- launch ----------------
extern "C" void kernel_launch(void* const* d_in, const int* in_sizes, int n_in,
                              void* d_out, int out_size) {
    const float* x     = (const float*)d_in[0];
    const void*  eidx  = d_in[1];
    const float* W0    = (const float*)d_in[2];
    const float* b0    = (const float*)d_in[3];
    const float* W1    = (const float*)d_in[4];
    const float* b1    = (const float*)d_in[5];
    const float* Wnb   = (const float*)d_in[6];
    const float* bnb   = (const float*)d_in[7];
    const float* Wself = (const float*)d_in[8];
    const float* bself = (const float*)d_in[9];
    const float* Watt  = (const float*)d_in[10];
    const float* batt  = (const float*)d_in[11];
    float* out = (float*)d_out;

    int N = in_sizes[0] / IN_DIM;
    int E = in_sizes[1] / 2;
    int NB = (N + 1023) / 1024;
    int GB = (N + 127) / 128;           // GEMM blocks
    int SB = (E + 255) / 256;           // scatter blocks

    static bool attr_set = false;
    if (!attr_set) {
        cudaFuncSetAttribute(k_gemm_scatter, cudaFuncAttributeMaxDynamicSharedMemorySize,
                             3 * GEMM_STG * sizeof(float));
        attr_set = true;
    }

    k_initprep<<<NB + 1, 1024>>>(eidx, W0, b0, W1, Wnb, bnb, Wself, bself,
                                 Watt, batt, N, NB);
    k_convert<<<(E + 255) / 256, 256>>>(eidx, E);
    k_scan1<<<NB, 1024>>>(N);
    k_scan3<<<NB, 1024>>>(N);
    k_gemm_scatter<<<GB + SB, 256, 3 * GEMM_STG * sizeof(float)>>>(x, eidx, N, E, GB);
    k_conv1<<<(N * 4 + 255) / 256, 256>>>(N);
    k_deg2<<<(N * 4 + 255) / 256, 256>>>(N);
    k_conv2<<<(N * 2 + 255) / 256, 256>>>(out, b1, N);
}